// round 11
// baseline (speedup 1.0000x reference)
#include <cuda_runtime.h>
#include <cuda_bf16.h>

// Problem constants (fixed shapes)
#define NF       64          // planar features
#define NG       4096        // graphs / segments
#define NNODES   1000000     // nodes per plane
#define NFI      256         // interaction features

#define TROWS    128         // nodes per tile (8 warps x 16-row m16n8k8 slabs)
#define SEGPB    8           // segments per block (sorted idx -> contiguous)
#define XPITCH   68          // x smem row pitch (floats): conflict-free
#define WPITCH   72          // W^T smem row pitch: conflict-free

// Dynamic smem layout (bytes)
#define XS_BYTES   (TROWS * XPITCH * 4)
#define OFF_XS0    0
#define OFF_XS1    (OFF_XS0 + XS_BYTES)          // 34816
#define OFF_WS     (OFF_XS1 + XS_BYTES)          // 69632
#define OFF_BS     (OFF_WS + 64 * WPITCH * 4)    // 88064
#define OFF_REDS   (OFF_BS + 256)                // 88320
#define OFF_REDA   (OFF_REDS + 2048)             // 90368
#define OFF_SS     (OFF_REDA + 2048)             // 92416
#define OFF_TAB    (OFF_SS + 48)                 // 92464 (8B-aligned)
#define SMEM_TOTAL (OFF_TAB + 1024 * 8)          // 100656

typedef unsigned long long ull;

// -------- device scratch (no cudaMalloc allowed) --------
__device__ int   d_segstart[3][NG + 1];
__device__ float d_pooled[3][NG * NF];

struct PlanePtrs {
    const float* x[3];
    const float* Wg[3];
    const float* bg[3];
    const void*  idx[3];
};

// ---- PTX helpers ----
__device__ __forceinline__ unsigned f2tf32(float v) {
    unsigned u; asm("cvt.rna.tf32.f32 %0, %1;" : "=r"(u) : "f"(v)); return u;
}
__device__ __forceinline__ void mma_tf32(float& d0, float& d1, float& d2, float& d3,
                                         unsigned a0, unsigned a1, unsigned a2, unsigned a3,
                                         unsigned b0, unsigned b1) {
    asm volatile("mma.sync.aligned.m16n8k8.row.col.f32.tf32.tf32.f32 "
                 "{%0,%1,%2,%3}, {%4,%5,%6,%7}, {%8,%9}, {%0,%1,%2,%3};"
                 : "+f"(d0), "+f"(d1), "+f"(d2), "+f"(d3)
                 : "r"(a0), "r"(a1), "r"(a2), "r"(a3), "r"(b0), "r"(b1));
}
__device__ __forceinline__ void cpa16(unsigned dst, const void* src) {
    asm volatile("cp.async.ca.shared.global [%0], [%1], 16;" :: "r"(dst), "l"(src));
}
__device__ __forceinline__ unsigned smem_u32(const void* p) {
    return (unsigned)__cvta_generic_to_shared(p);
}

// ---- packed f32x2 primitives (Blackwell dual-fp32 pipe) ----
__device__ __forceinline__ ull pk2(float a, float b) {
    ull r; asm("mov.b64 %0, {%1, %2};" : "=l"(r) : "f"(a), "f"(b)); return r;
}
__device__ __forceinline__ void upk2(ull v, float& a, float& b) {
    asm("mov.b64 {%0, %1}, %2;" : "=f"(a), "=f"(b) : "l"(v));
}
__device__ __forceinline__ ull add2_(ull a, ull b) {
    ull r; asm("add.rn.f32x2 %0, %1, %2;" : "=l"(r) : "l"(a), "l"(b)); return r;
}
__device__ __forceinline__ ull fma2_(ull a, ull b, ull c) {
    ull r; asm("fma.rn.f32x2 %0, %1, %2, %3;" : "=l"(r) : "l"(a), "l"(b), "l"(c)); return r;
}

// ---- LUT gate: F(z) = exp(sigmoid(z)), piecewise-linear, 1024 bins on [-16,16].
// Per gate: FFMA + F2I + 2x IMNMX + LDS.64 + FFMA. Interp err <= ~3e-5 rel.
// Edge slopes ~0, so linear extrapolation beyond +-16 (13 sigma) is benign.
__device__ __forceinline__ float gtab(const float2* __restrict__ tab, float z) {
    float t = fmaf(z, 32.0f, 512.0f);
    int i = __float2int_rd(t);
    i = min(max(i, 0), 1023);
    float2 ab = tab[i];
    return fmaf(ab.y, z, ab.x);
}

// ---------------------------------------------------------------------------
// Kernel A: per-plane segment offsets via binary search on sorted idx.
// ---------------------------------------------------------------------------
__global__ void segstart_kernel(PlanePtrs p, int n)
{
    int g = blockIdx.x * blockDim.x + threadIdx.x;
    int plane = blockIdx.y;
    if (g > NG) return;

    const int* a32 = (const int*)p.idx[plane];
    bool is64 = (a32[400001] == 0);      // int64 high word 0; int32 value ~1639
    const long long* a64 = (const long long*)p.idx[plane];

    int lo = 0, hi = n;
    while (lo < hi) {
        int mid = (lo + hi) >> 1;
        long long v = is64 ? a64[mid] : (long long)a32[mid];
        if (v < (long long)g) lo = mid + 1; else hi = mid;
    }
    d_segstart[plane][g] = lo;
}

// ---------------------------------------------------------------------------
// Kernel B: fused attention pool. One block owns SEGPB consecutive segments;
// W + gate LUT staged once per block; cp.async pipeline runs continuously
// across segment boundaries. tf32 MMA gate GEMM + LUT exp(sigmoid) epilogue.
// ---------------------------------------------------------------------------
__global__ __launch_bounds__(256, 2)
void attn_pool_kernel(PlanePtrs p)
{
    extern __shared__ char smem[];
    float*    xs[2]; xs[0] = (float*)(smem + OFF_XS0); xs[1] = (float*)(smem + OFF_XS1);
    unsigned* Wsu   = (unsigned*)(smem + OFF_WS);
    float*    bs    = (float*)(smem + OFF_BS);
    float*    red_s = (float*)(smem + OFF_REDS);
    float*    red_a = (float*)(smem + OFF_REDA);
    int*      ss    = (int*)(smem + OFF_SS);
    const float2* tab = (const float2*)(smem + OFF_TAB);

    const int plane   = blockIdx.y;
    const int segbase = blockIdx.x * SEGPB;
    const int tid  = threadIdx.x;
    const int wid  = tid >> 5;
    const int lane = tid & 31;
    const int gq   = lane >> 2;      // fragment row 0..7
    const int tig  = lane & 3;       // thread-in-group

    // Segment boundary cache for this block's range.
    if (tid <= SEGPB) ss[tid] = d_segstart[plane][segbase + tid];
    __syncthreads();

    const float* __restrict__ x = p.x[plane];

    // Lookahead tile cursor over (segment, tile) pairs; skips empty segments.
    int pseg = 0, pt = 0;
    while (pseg < SEGPB && ss[pseg] + pt * TROWS >= ss[pseg + 1]) { pseg++; pt = 0; }

    // Prefetch first tile into buf 0.
    if (pseg < SEGPB) {
        unsigned dstb = smem_u32(xs[0]);
        int nbase = ss[pseg] + pt * TROWS;
        for (int c = tid; c < TROWS * 16; c += 256) {
            int row = c >> 4, col4 = c & 15;
            int gr = min(nbase + row, NNODES - 1);
            cpa16(dstb + (unsigned)(row * XPITCH + col4 * 4) * 4u,
                  x + (size_t)gr * NF + col4 * 4);
        }
        asm volatile("cp.async.commit_group;");
        pt++;
        while (pseg < SEGPB && ss[pseg] + pt * TROWS >= ss[pseg + 1]) { pseg++; pt = 0; }
    }

    // Build F(z)=exp(sigmoid(z)) boundary values in xs[1] scratch (not yet
    // claimed by the pipeline), while tile 0 is in flight.
    {
        float* Ft = xs[1];
        for (int i = tid; i <= 1024; i += 256) {
            float zl = (i - 512) * 0.03125f;
            float g  = __fdividef(1.0f, 1.0f + __expf(-zl));
            Ft[i] = __expf(g);
        }
    }
    __syncthreads();
    // Finalize (A', B) per interval; stage W^T (RNA tf32) + bias.
    {
        const float* Ft = xs[1];
        float2* tabw = (float2*)(smem + OFF_TAB);
        for (int i = tid; i < 1024; i += 256) {
            float zl = (i - 512) * 0.03125f;
            float B  = (Ft[i + 1] - Ft[i]) * 32.0f;
            tabw[i] = make_float2(fmaf(-B, zl, Ft[i]), B);
        }
        const float* Wg = p.Wg[plane];
        for (int i = tid; i < NF * NF; i += 256) {
            int f = i >> 6, k = i & 63;
            Wsu[k * WPITCH + f] = f2tf32(Wg[i]);
        }
        if (tid < NF) bs[tid] = p.bg[plane][tid];
    }
    __syncthreads();   // table + W visible before mainloop (t=0 reuses xs[1])

    const int r0 = wid * 16;
    int tc = 0;                       // global tile counter -> buffer select

    ull spk[8], apk[8];
#pragma unroll
    for (int nt = 0; nt < 8; ++nt) { spk[nt] = pk2(0.f, 0.f); apk[nt] = pk2(0.f, 0.f); }

    for (int seg = 0; seg < SEGPB; ++seg) {
        const int s0 = ss[seg], s1 = ss[seg + 1];
        if (s1 <= s0) {
            if (tid < NF) d_pooled[plane][(segbase + seg) * NF + tid] = 0.f;
            continue;
        }
        const int ntiles = (s1 - s0 + TROWS - 1) / TROWS;

        for (int t = 0; t < ntiles; ++t) {
            const int buf = tc & 1;
            // Prefetch cursor tile into the other buffer (cross-segment OK).
            if (pseg < SEGPB) {
                unsigned dstb = smem_u32(xs[buf ^ 1]);
                int nbase = ss[pseg] + pt * TROWS;
                for (int c = tid; c < TROWS * 16; c += 256) {
                    int row = c >> 4, col4 = c & 15;
                    int gr = min(nbase + row, NNODES - 1);
                    cpa16(dstb + (unsigned)(row * XPITCH + col4 * 4) * 4u,
                          x + (size_t)gr * NF + col4 * 4);
                }
                asm volatile("cp.async.commit_group;");
                pt++;
                while (pseg < SEGPB && ss[pseg] + pt * TROWS >= ss[pseg + 1]) { pseg++; pt = 0; }
                asm volatile("cp.async.wait_group 1;");
            } else {
                asm volatile("cp.async.wait_group 0;");
            }
            __syncthreads();

            const float* xb    = xs[buf];
            const float* arow0 = xb + (r0 + gq) * XPITCH;
            const float* arow1 = xb + (r0 + gq + 8) * XPITCH;

            // A fragments: RNA tf32 conversion.
            unsigned a[8][4];
#pragma unroll
            for (int k = 0; k < 8; ++k) {
                a[k][0] = f2tf32(arow0[8 * k + tig]);
                a[k][1] = f2tf32(arow1[8 * k + tig]);
                a[k][2] = f2tf32(arow0[8 * k + tig + 4]);
                a[k][3] = f2tf32(arow1[8 * k + tig + 4]);
            }

            const int n0 = s0 + t * TROWS + r0 + gq;
            const bool v0 = (n0 < s1);
            const bool v1 = (n0 + 8 < s1);

#pragma unroll
            for (int nt = 0; nt < 8; ++nt) {
                const int f0 = nt * 8;
                float z0 = 0.f, z1 = 0.f, z2 = 0.f, z3 = 0.f;
#pragma unroll
                for (int k = 0; k < 8; ++k) {
                    unsigned b0 = Wsu[(8 * k + tig) * WPITCH + f0 + gq];
                    unsigned b1 = Wsu[(8 * k + tig + 4) * WPITCH + f0 + gq];
                    mma_tf32(z0, z1, z2, z3, a[k][0], a[k][1], a[k][2], a[k][3], b0, b1);
                }
                ull bb   = *(const ull*)&bs[f0 + 2 * tig];
                ull zz01 = add2_(pk2(z0, z1), bb);
                ull zz23 = add2_(pk2(z2, z3), bb);
                float za0, za1, za2, za3;
                upk2(zz01, za0, za1);
                upk2(zz23, za2, za3);
                float e0 = gtab(tab, za0);
                float e1 = gtab(tab, za1);
                float e2 = gtab(tab, za2);
                float e3 = gtab(tab, za3);
                if (!v0) { e0 = 0.f; e1 = 0.f; }
                if (!v1) { e2 = 0.f; e3 = 0.f; }
                ull e01 = pk2(e0, e1);
                ull e23 = pk2(e2, e3);
                ull x01 = *(const ull*)&arow0[f0 + 2 * tig];
                ull x23 = *(const ull*)&arow1[f0 + 2 * tig];
                spk[nt] = add2_(spk[nt], add2_(e01, e23));
                apk[nt] = fma2_(e01, x01, apk[nt]);
                apk[nt] = fma2_(e23, x23, apk[nt]);
            }
            __syncthreads();   // guard xs[buf] before its next refill
            tc++;
        }

        // Per-segment reduction: shfl across the 8 quad-group rows, then
        // cross-warp via smem; reset accumulators for the next segment.
#pragma unroll
        for (int nt = 0; nt < 8; ++nt) {
            float sx, sy, ax, ay;
            upk2(spk[nt], sx, sy);
            upk2(apk[nt], ax, ay);
#pragma unroll
            for (int m = 4; m < 32; m <<= 1) {
                sx += __shfl_xor_sync(0xffffffffu, sx, m);
                sy += __shfl_xor_sync(0xffffffffu, sy, m);
                ax += __shfl_xor_sync(0xffffffffu, ax, m);
                ay += __shfl_xor_sync(0xffffffffu, ay, m);
            }
            if (gq == 0) {
                int f = nt * 8 + 2 * tig;
                red_s[wid * NF + f]     = sx;
                red_s[wid * NF + f + 1] = sy;
                red_a[wid * NF + f]     = ax;
                red_a[wid * NF + f + 1] = ay;
            }
            spk[nt] = pk2(0.f, 0.f);
            apk[nt] = pk2(0.f, 0.f);
        }
        __syncthreads();

        if (tid < NF) {
            float S = 0.f, A = 0.f;
#pragma unroll
            for (int w = 0; w < 8; ++w) {
                S += red_s[w * NF + tid];
                A += red_a[w * NF + tid];
            }
            d_pooled[plane][(segbase + seg) * NF + tid] = A / S;
        }
    }
}

// ---------------------------------------------------------------------------
// Kernel C: out[G, 256] = concat(pooled)[G, 192] @ W_out^T + b_out
// ---------------------------------------------------------------------------
__global__ __launch_bounds__(256)
void out_gemm_kernel(const float* __restrict__ W_out,
                     const float* __restrict__ b_out,
                     float* __restrict__ out)
{
    const int o  = threadIdx.x;
    const int g0 = blockIdx.x * 16;

    __shared__ float hs[16][192];
    for (int i = threadIdx.x; i < 16 * 192; i += 256) {
        int gg = i / 192, k = i % 192;
        hs[gg][k] = d_pooled[k >> 6][(g0 + gg) * NF + (k & 63)];
    }
    __syncthreads();

    float accv[16];
    const float bo = b_out[o];
#pragma unroll
    for (int gg = 0; gg < 16; ++gg) accv[gg] = bo;

    const float4* wrow = (const float4*)(W_out + o * 192);
    for (int k4 = 0; k4 < 48; ++k4) {
        float4 w = wrow[k4];
        int k = k4 * 4;
#pragma unroll
        for (int gg = 0; gg < 16; ++gg) {
            accv[gg] += w.x * hs[gg][k + 0];
            accv[gg] += w.y * hs[gg][k + 1];
            accv[gg] += w.z * hs[gg][k + 2];
            accv[gg] += w.w * hs[gg][k + 3];
        }
    }
#pragma unroll
    for (int gg = 0; gg < 16; ++gg)
        out[(g0 + gg) * NFI + o] = accv[gg];
}

// ---------------------------------------------------------------------------
// Launch: classify inputs by element count (order-robust), then 3 kernels.
// ---------------------------------------------------------------------------
extern "C" void kernel_launch(void* const* d_in, const int* in_sizes, int n_in,
                              void* d_out, int out_size)
{
    PlanePtrs p;
    const float* W_out = nullptr;
    const float* b_out = nullptr;
    int nx = 0, nw = 0, nb = 0, ni = 0;

    for (int i = 0; i < n_in; ++i) {
        switch (in_sizes[i]) {
            case NNODES * NF:      if (nx < 3) p.x[nx++]   = (const float*)d_in[i]; break;
            case NF * NF:          if (nw < 3) p.Wg[nw++]  = (const float*)d_in[i]; break;
            case NF:               if (nb < 3) p.bg[nb++]  = (const float*)d_in[i]; break;
            case NNODES:           if (ni < 3) p.idx[ni++] = d_in[i];               break;
            case NFI * 3 * NF:     W_out = (const float*)d_in[i];                   break;
            case NFI:              b_out = (const float*)d_in[i];                   break;
            default: break;
        }
    }

    cudaFuncSetAttribute(attn_pool_kernel,
                         cudaFuncAttributeMaxDynamicSharedMemorySize, SMEM_TOTAL);

    dim3 gseg((NG + 1 + 255) / 256, 3);
    segstart_kernel<<<gseg, 256>>>(p, NNODES);

    dim3 gattn(NG / SEGPB, 3);
    attn_pool_kernel<<<gattn, 256, SMEM_TOTAL>>>(p);

    out_gemm_kernel<<<NG / 16, 256>>>(W_out, b_out, (float*)d_out);
    (void)out_size;
}

// round 12
// speedup vs baseline: 1.0575x; 1.0575x over previous
#include <cuda_runtime.h>
#include <cuda_bf16.h>

// Problem constants (fixed shapes)
#define NF       64          // planar features
#define NG       4096        // graphs / segments
#define NNODES   1000000     // nodes per plane
#define NFI      256         // interaction features

#define TROWS    128         // nodes per tile (8 warps x 16-row m16n8k8 slabs)
#define SEGPB    8           // segments per block (sorted idx -> contiguous)
#define XPITCH   68          // x smem row pitch (floats): conflict-free
#define WFSTRIDE 132         // per-lane W-fragment row stride (words): 4-bank shift

// Dynamic smem layout (bytes)
#define XS_BYTES   (TROWS * XPITCH * 4)
#define OFF_XS0    0
#define OFF_XS1    (OFF_XS0 + XS_BYTES)          // 34816
#define OFF_WF     (OFF_XS1 + XS_BYTES)          // 69632  (32*132*4 = 16896)
#define OFF_BS     (OFF_WF + 32 * WFSTRIDE * 4)  // 86528
#define OFF_REDS   (OFF_BS + 256)                // 86784
#define OFF_REDA   (OFF_REDS + 2048)             // 88832
#define OFF_SS     (OFF_REDA + 2048)             // 90880
#define SMEM_TOTAL (OFF_SS + (SEGPB + 1) * 4 + 12)   // 90928

typedef unsigned long long ull;

// -------- device scratch (no cudaMalloc allowed) --------
__device__ int   d_segstart[3][NG + 1];
__device__ float d_pooled[3][NG * NF];

struct PlanePtrs {
    const float* x[3];
    const float* Wg[3];
    const float* bg[3];
    const void*  idx[3];
};

// ---- PTX helpers ----
__device__ __forceinline__ unsigned f2tf32(float v) {
    unsigned u; asm("cvt.rna.tf32.f32 %0, %1;" : "=r"(u) : "f"(v)); return u;
}
__device__ __forceinline__ void mma_tf32(float& d0, float& d1, float& d2, float& d3,
                                         unsigned a0, unsigned a1, unsigned a2, unsigned a3,
                                         unsigned b0, unsigned b1) {
    asm volatile("mma.sync.aligned.m16n8k8.row.col.f32.tf32.tf32.f32 "
                 "{%0,%1,%2,%3}, {%4,%5,%6,%7}, {%8,%9}, {%0,%1,%2,%3};"
                 : "+f"(d0), "+f"(d1), "+f"(d2), "+f"(d3)
                 : "r"(a0), "r"(a1), "r"(a2), "r"(a3), "r"(b0), "r"(b1));
}
__device__ __forceinline__ void cpa16(unsigned dst, const void* src) {
    asm volatile("cp.async.ca.shared.global [%0], [%1], 16;" :: "r"(dst), "l"(src));
}
__device__ __forceinline__ unsigned smem_u32(const void* p) {
    return (unsigned)__cvta_generic_to_shared(p);
}

// ---- packed f32x2 primitives (Blackwell dual-fp32 pipe) ----
__device__ __forceinline__ ull pk2(float a, float b) {
    ull r; asm("mov.b64 %0, {%1, %2};" : "=l"(r) : "f"(a), "f"(b)); return r;
}
__device__ __forceinline__ void upk2(ull v, float& a, float& b) {
    asm("mov.b64 {%0, %1}, %2;" : "=f"(a), "=f"(b) : "l"(v));
}
__device__ __forceinline__ ull mul2_(ull a, ull b) {
    ull r; asm("mul.rn.f32x2 %0, %1, %2;" : "=l"(r) : "l"(a), "l"(b)); return r;
}
__device__ __forceinline__ ull add2_(ull a, ull b) {
    ull r; asm("add.rn.f32x2 %0, %1, %2;" : "=l"(r) : "l"(a), "l"(b)); return r;
}
__device__ __forceinline__ ull fma2_(ull a, ull b, ull c) {
    ull r; asm("fma.rn.f32x2 %0, %1, %2, %3;" : "=l"(r) : "l"(a), "l"(b), "l"(c)); return r;
}

// ---- packed MUFU-free gate: returns (exp(sigmoid(z0)), exp(sigmoid(z1))) ----
__device__ __forceinline__ ull gate_exp2(ull z) {
    const ull NL2E = pk2(-1.4426950408889634f, -1.4426950408889634f);
    const ull MAG  = pk2(12582912.0f, 12582912.0f);
    const ull NMAG = pk2(-12582912.0f, -12582912.0f);
    const ull NONE = pk2(-1.0f, -1.0f);
    const ull ONE  = pk2(1.0f, 1.0f);
    const ull TWO  = pk2(2.0f, 2.0f);

    // u = exp(-z): magic round + degree-5 2^f poly. Range reduction must be
    // two EXACT steps (nf = fi - MAG; fr = t - nf): fusing rounds the
    // fraction away at |.|~1.25e7 (the R7/R8 3.8% bug).
    ull t  = mul2_(z, NL2E);
    ull fi = add2_(t, MAG);
    ull nf = add2_(fi, NMAG);                  // exact small integer
    ull fr = fma2_(nf, NONE, t);               // t - n, exact
    ull p  = pk2(1.33335581e-3f, 1.33335581e-3f);
    p = fma2_(p, fr, pk2(9.61812910e-3f, 9.61812910e-3f));
    p = fma2_(p, fr, pk2(5.55041087e-2f, 5.55041087e-2f));
    p = fma2_(p, fr, pk2(2.40226507e-1f, 2.40226507e-1f));
    p = fma2_(p, fr, pk2(6.93147181e-1f, 6.93147181e-1f));
    p = fma2_(p, fr, ONE);
    float fi0, fi1, p0, p1;
    upk2(fi, fi0, fi1); upk2(p, p0, p1);
    int n0 = (__float_as_int(fi0) - 0x4B400000) << 23;
    int n1 = (__float_as_int(fi1) - 0x4B400000) << 23;
    float u0 = __int_as_float(__float_as_int(p0) + n0);
    float u1 = __int_as_float(__float_as_int(p1) + n1);

    // g = 1/(1+u): bit-trick seed + 2 packed Newton (~6e-6 rel err)
    ull d = add2_(ONE, pk2(u0, u1));
    float d0, d1; upk2(d, d0, d1);
    float r0 = __int_as_float(0x7EF311C3u - __float_as_int(d0));
    float r1 = __int_as_float(0x7EF311C3u - __float_as_int(d1));
    ull r  = pk2(r0, r1);
    ull nd = mul2_(d, NONE);
    r = mul2_(r, fma2_(nd, r, TWO));
    r = mul2_(r, fma2_(nd, r, TWO));

    // exp(g), g in (0,1): degree-5 Taylor at 0.5, err ~4e-5
    ull s = add2_(r, pk2(-0.5f, -0.5f));
    ull q = pk2(1.37393439e-2f, 1.37393439e-2f);
    q = fma2_(q, s, pk2(6.86967196e-2f, 6.86967196e-2f));
    q = fma2_(q, s, pk2(2.74786878e-1f, 2.74786878e-1f));
    q = fma2_(q, s, pk2(8.24360635e-1f, 8.24360635e-1f));
    q = fma2_(q, s, pk2(1.64872127f, 1.64872127f));
    q = fma2_(q, s, pk2(1.64872127f, 1.64872127f));
    return q;
}

// ---------------------------------------------------------------------------
// Kernel A: per-plane segment offsets via binary search on sorted idx.
// ---------------------------------------------------------------------------
__global__ void segstart_kernel(PlanePtrs p, int n)
{
    int g = blockIdx.x * blockDim.x + threadIdx.x;
    int plane = blockIdx.y;
    if (g > NG) return;

    const int* a32 = (const int*)p.idx[plane];
    bool is64 = (a32[400001] == 0);      // int64 high word 0; int32 value ~1639
    const long long* a64 = (const long long*)p.idx[plane];

    int lo = 0, hi = n;
    while (lo < hi) {
        int mid = (lo + hi) >> 1;
        long long v = is64 ? a64[mid] : (long long)a32[mid];
        if (v < (long long)g) lo = mid + 1; else hi = mid;
    }
    d_segstart[plane][g] = lo;
}

// ---------------------------------------------------------------------------
// Kernel B: fused attention pool (one plane per launch). One block owns SEGPB
// consecutive segments; cp.async pipeline runs continuously across segment
// boundaries. tf32 MMA gate GEMM + packed-poly exp(sigmoid) epilogue.
//
// NEW: W is pre-arranged ONCE per block into a per-lane fragment table
// Wf[lane][128]: exactly the 128 tf32 B-fragment words lane (gq,tig) needs,
// ordered (nt, k, b0/b1), row stride 132 words (conflict-free LDS.128).
// B loads per thread-tile: 128x LDS.32 -> 32x LDS.128 (same values).
// ---------------------------------------------------------------------------
__global__ __launch_bounds__(256, 2)
void attn_pool_kernel(PlanePtrs p, int plane)
{
    extern __shared__ char smem[];
    float*    xs[2]; xs[0] = (float*)(smem + OFF_XS0); xs[1] = (float*)(smem + OFF_XS1);
    unsigned* Wf    = (unsigned*)(smem + OFF_WF);
    float*    bs    = (float*)(smem + OFF_BS);
    float*    red_s = (float*)(smem + OFF_REDS);
    float*    red_a = (float*)(smem + OFF_REDA);
    int*      ss    = (int*)(smem + OFF_SS);

    const int segbase = blockIdx.x * SEGPB;
    const int tid  = threadIdx.x;
    const int wid  = tid >> 5;
    const int lane = tid & 31;
    const int gq   = lane >> 2;      // fragment row 0..7
    const int tig  = lane & 3;       // thread-in-group

    // Segment boundary cache for this block's range.
    if (tid <= SEGPB) ss[tid] = d_segstart[plane][segbase + tid];
    __syncthreads();

    const float* __restrict__ x = p.x[plane];

    // Lookahead tile cursor over (segment, tile) pairs; skips empty segments.
    int pseg = 0, pt = 0;
    while (pseg < SEGPB && ss[pseg] + pt * TROWS >= ss[pseg + 1]) { pseg++; pt = 0; }

    // Prefetch first tile into buf 0.
    if (pseg < SEGPB) {
        unsigned dstb = smem_u32(xs[0]);
        int nbase = ss[pseg] + pt * TROWS;
        for (int c = tid; c < TROWS * 16; c += 256) {
            int row = c >> 4, col4 = c & 15;
            int gr = min(nbase + row, NNODES - 1);
            cpa16(dstb + (unsigned)(row * XPITCH + col4 * 4) * 4u,
                  x + (size_t)gr * NF + col4 * 4);
        }
        asm volatile("cp.async.commit_group;");
        pt++;
        while (pseg < SEGPB && ss[pseg] + pt * TROWS >= ss[pseg + 1]) { pseg++; pt = 0; }
    }

    // Build per-lane W fragment table + bias while tile 0 is in flight.
    // Wf[c][w]: c = lane class (gq<<2|tig); w = nt*16 + k*2 + s;
    // value = tf32(Wg[feat=nt*8+gq][kk=k*8+tig+4s])  (same data as R10's Wsu).
    {
        const float* Wg = p.Wg[plane];
        for (int i = tid; i < 32 * 128; i += 256) {
            int c = i >> 7, w = i & 127;
            int gq_ = c >> 2, tig_ = c & 3;
            int nt = w >> 4, k = (w >> 1) & 7, s = w & 1;
            Wf[c * WFSTRIDE + w] = f2tf32(Wg[(nt * 8 + gq_) * 64 + k * 8 + tig_ + s * 4]);
        }
        if (tid < NF) bs[tid] = p.bg[plane][tid];
    }

    const int r0 = wid * 16;
    int tc = 0;                       // global tile counter -> buffer select
    const uint4* wfl = (const uint4*)(Wf + lane * WFSTRIDE);   // 16B-aligned

    ull spk[8], apk[8];
#pragma unroll
    for (int nt = 0; nt < 8; ++nt) { spk[nt] = pk2(0.f, 0.f); apk[nt] = pk2(0.f, 0.f); }

    for (int seg = 0; seg < SEGPB; ++seg) {
        const int s0 = ss[seg], s1 = ss[seg + 1];
        if (s1 <= s0) {
            if (tid < NF) d_pooled[plane][(segbase + seg) * NF + tid] = 0.f;
            continue;
        }
        const int ntiles = (s1 - s0 + TROWS - 1) / TROWS;

        for (int t = 0; t < ntiles; ++t) {
            const int buf = tc & 1;
            // Prefetch cursor tile into the other buffer (cross-segment OK).
            if (pseg < SEGPB) {
                unsigned dstb = smem_u32(xs[buf ^ 1]);
                int nbase = ss[pseg] + pt * TROWS;
                for (int c = tid; c < TROWS * 16; c += 256) {
                    int row = c >> 4, col4 = c & 15;
                    int gr = min(nbase + row, NNODES - 1);
                    cpa16(dstb + (unsigned)(row * XPITCH + col4 * 4) * 4u,
                          x + (size_t)gr * NF + col4 * 4);
                }
                asm volatile("cp.async.commit_group;");
                pt++;
                while (pseg < SEGPB && ss[pseg] + pt * TROWS >= ss[pseg + 1]) { pseg++; pt = 0; }
                asm volatile("cp.async.wait_group 1;");
            } else {
                asm volatile("cp.async.wait_group 0;");
            }
            __syncthreads();   // also publishes Wf/bs on the first iteration

            const float* xb    = xs[buf];
            const float* arow0 = xb + (r0 + gq) * XPITCH;
            const float* arow1 = xb + (r0 + gq + 8) * XPITCH;

            // A fragments: RNA tf32 conversion.
            unsigned a[8][4];
#pragma unroll
            for (int k = 0; k < 8; ++k) {
                a[k][0] = f2tf32(arow0[8 * k + tig]);
                a[k][1] = f2tf32(arow1[8 * k + tig]);
                a[k][2] = f2tf32(arow0[8 * k + tig + 4]);
                a[k][3] = f2tf32(arow1[8 * k + tig + 4]);
            }

            const int n0 = s0 + t * TROWS + r0 + gq;
            const bool v0 = (n0 < s1);
            const bool v1 = (n0 + 8 < s1);

#pragma unroll
            for (int nt = 0; nt < 8; ++nt) {
                const int f0 = nt * 8;
                // B fragments for this n-tile: 4x LDS.128, conflict-free.
                uint4 u0 = wfl[nt * 4 + 0];
                uint4 u1 = wfl[nt * 4 + 1];
                uint4 u2 = wfl[nt * 4 + 2];
                uint4 u3 = wfl[nt * 4 + 3];
                float z0 = 0.f, z1 = 0.f, z2 = 0.f, z3 = 0.f;
                mma_tf32(z0, z1, z2, z3, a[0][0], a[0][1], a[0][2], a[0][3], u0.x, u0.y);
                mma_tf32(z0, z1, z2, z3, a[1][0], a[1][1], a[1][2], a[1][3], u0.z, u0.w);
                mma_tf32(z0, z1, z2, z3, a[2][0], a[2][1], a[2][2], a[2][3], u1.x, u1.y);
                mma_tf32(z0, z1, z2, z3, a[3][0], a[3][1], a[3][2], a[3][3], u1.z, u1.w);
                mma_tf32(z0, z1, z2, z3, a[4][0], a[4][1], a[4][2], a[4][3], u2.x, u2.y);
                mma_tf32(z0, z1, z2, z3, a[5][0], a[5][1], a[5][2], a[5][3], u2.z, u2.w);
                mma_tf32(z0, z1, z2, z3, a[6][0], a[6][1], a[6][2], a[6][3], u3.x, u3.y);
                mma_tf32(z0, z1, z2, z3, a[7][0], a[7][1], a[7][2], a[7][3], u3.z, u3.w);

                ull bb  = *(const ull*)&bs[f0 + 2 * tig];
                ull e01 = gate_exp2(add2_(pk2(z0, z1), bb));   // (row n0,   feats f0+2tig,+1)
                ull e23 = gate_exp2(add2_(pk2(z2, z3), bb));   // (row n0+8)
                if (!v0) e01 = 0ull;
                if (!v1) e23 = 0ull;
                ull x01 = *(const ull*)&arow0[f0 + 2 * tig];
                ull x23 = *(const ull*)&arow1[f0 + 2 * tig];
                spk[nt] = add2_(spk[nt], add2_(e01, e23));
                apk[nt] = fma2_(e01, x01, apk[nt]);
                apk[nt] = fma2_(e23, x23, apk[nt]);
            }
            __syncthreads();   // guard xs[buf] before its next refill
            tc++;
        }

        // Per-segment reduction: shfl across the 8 quad-group rows, then
        // cross-warp via smem; reset accumulators for the next segment.
#pragma unroll
        for (int nt = 0; nt < 8; ++nt) {
            float sx, sy, ax, ay;
            upk2(spk[nt], sx, sy);
            upk2(apk[nt], ax, ay);
#pragma unroll
            for (int m = 4; m < 32; m <<= 1) {
                sx += __shfl_xor_sync(0xffffffffu, sx, m);
                sy += __shfl_xor_sync(0xffffffffu, sy, m);
                ax += __shfl_xor_sync(0xffffffffu, ax, m);
                ay += __shfl_xor_sync(0xffffffffu, ay, m);
            }
            if (gq == 0) {
                int f = nt * 8 + 2 * tig;
                red_s[wid * NF + f]     = sx;
                red_s[wid * NF + f + 1] = sy;
                red_a[wid * NF + f]     = ax;
                red_a[wid * NF + f + 1] = ay;
            }
            spk[nt] = pk2(0.f, 0.f);
            apk[nt] = pk2(0.f, 0.f);
        }
        __syncthreads();

        if (tid < NF) {
            float S = 0.f, A = 0.f;
#pragma unroll
            for (int w = 0; w < 8; ++w) {
                S += red_s[w * NF + tid];
                A += red_a[w * NF + tid];
            }
            d_pooled[plane][(segbase + seg) * NF + tid] = A / S;
        }
    }
}

// ---------------------------------------------------------------------------
// Kernel C: out[G, 256] = concat(pooled)[G, 192] @ W_out^T + b_out
// ---------------------------------------------------------------------------
__global__ __launch_bounds__(256)
void out_gemm_kernel(const float* __restrict__ W_out,
                     const float* __restrict__ b_out,
                     float* __restrict__ out)
{
    const int o  = threadIdx.x;
    const int g0 = blockIdx.x * 16;

    __shared__ float hs[16][192];
    for (int i = threadIdx.x; i < 16 * 192; i += 256) {
        int gg = i / 192, k = i % 192;
        hs[gg][k] = d_pooled[k >> 6][(g0 + gg) * NF + (k & 63)];
    }
    __syncthreads();

    float accv[16];
    const float bo = b_out[o];
#pragma unroll
    for (int gg = 0; gg < 16; ++gg) accv[gg] = bo;

    const float4* wrow = (const float4*)(W_out + o * 192);
    for (int k4 = 0; k4 < 48; ++k4) {
        float4 w = wrow[k4];
        int k = k4 * 4;
#pragma unroll
        for (int gg = 0; gg < 16; ++gg) {
            accv[gg] += w.x * hs[gg][k + 0];
            accv[gg] += w.y * hs[gg][k + 1];
            accv[gg] += w.z * hs[gg][k + 2];
            accv[gg] += w.w * hs[gg][k + 3];
        }
    }
#pragma unroll
    for (int gg = 0; gg < 16; ++gg)
        out[(g0 + gg) * NFI + o] = accv[gg];
}

// ---------------------------------------------------------------------------
// Launch: classify inputs by element count (order-robust), then kernels.
// attn is launched once per plane (observability + per-plane grids).
// ---------------------------------------------------------------------------
extern "C" void kernel_launch(void* const* d_in, const int* in_sizes, int n_in,
                              void* d_out, int out_size)
{
    PlanePtrs p;
    const float* W_out = nullptr;
    const float* b_out = nullptr;
    int nx = 0, nw = 0, nb = 0, ni = 0;

    for (int i = 0; i < n_in; ++i) {
        switch (in_sizes[i]) {
            case NNODES * NF:      if (nx < 3) p.x[nx++]   = (const float*)d_in[i]; break;
            case NF * NF:          if (nw < 3) p.Wg[nw++]  = (const float*)d_in[i]; break;
            case NF:               if (nb < 3) p.bg[nb++]  = (const float*)d_in[i]; break;
            case NNODES:           if (ni < 3) p.idx[ni++] = d_in[i];               break;
            case NFI * 3 * NF:     W_out = (const float*)d_in[i];                   break;
            case NFI:              b_out = (const float*)d_in[i];                   break;
            default: break;
        }
    }

    cudaFuncSetAttribute(attn_pool_kernel,
                         cudaFuncAttributeMaxDynamicSharedMemorySize, SMEM_TOTAL);

    dim3 gseg((NG + 1 + 255) / 256, 3);
    segstart_kernel<<<gseg, 256>>>(p, NNODES);

    for (int plane = 0; plane < 3; ++plane)
        attn_pool_kernel<<<NG / SEGPB, 256, SMEM_TOTAL>>>(p, plane);

    out_gemm_kernel<<<NG / 16, 256>>>(W_out, b_out, (float*)d_out);
    (void)out_size;
}

// round 13
// speedup vs baseline: 1.3015x; 1.2307x over previous
#include <cuda_runtime.h>
#include <cuda_bf16.h>

// Problem constants (fixed shapes)
#define NF       64          // planar features
#define NG       4096        // graphs / segments
#define NNODES   1000000     // nodes per plane
#define NFI      256         // interaction features

#define TROWS    128         // nodes per tile (8 warps x 16-row m16n8k8 slabs)
#define SEGPB    8           // segments per block (sorted idx -> contiguous)
#define XPITCH   68          // x smem row pitch (floats): conflict-free
#define WFSTRIDE 132         // per-lane W-fragment row stride (words): 4-bank shift

// Dynamic smem layout (bytes)
#define XS_BYTES   (TROWS * XPITCH * 4)
#define OFF_XS0    0
#define OFF_XS1    (OFF_XS0 + XS_BYTES)          // 34816
#define OFF_WF     (OFF_XS1 + XS_BYTES)          // 69632  (32*132*4 = 16896)
#define OFF_BS     (OFF_WF + 32 * WFSTRIDE * 4)  // 86528
#define OFF_REDS   (OFF_BS + 256)                // 86784
#define OFF_REDA   (OFF_REDS + 2048)             // 88832
#define OFF_SS     (OFF_REDA + 2048)             // 90880
#define SMEM_TOTAL (OFF_SS + (SEGPB + 1) * 4 + 12)   // 90928

typedef unsigned long long ull;

// -------- device scratch (no cudaMalloc allowed) --------
__device__ int   d_segstart[3][NG + 1];
__device__ float d_pooled[3][NG * NF];

struct PlanePtrs {
    const float* x[3];
    const float* Wg[3];
    const float* bg[3];
    const void*  idx[3];
};

// ---- PTX helpers ----
__device__ __forceinline__ unsigned f2tf32(float v) {
    unsigned u; asm("cvt.rna.tf32.f32 %0, %1;" : "=r"(u) : "f"(v)); return u;
}
__device__ __forceinline__ void mma_tf32(float& d0, float& d1, float& d2, float& d3,
                                         unsigned a0, unsigned a1, unsigned a2, unsigned a3,
                                         unsigned b0, unsigned b1) {
    asm volatile("mma.sync.aligned.m16n8k8.row.col.f32.tf32.tf32.f32 "
                 "{%0,%1,%2,%3}, {%4,%5,%6,%7}, {%8,%9}, {%0,%1,%2,%3};"
                 : "+f"(d0), "+f"(d1), "+f"(d2), "+f"(d3)
                 : "r"(a0), "r"(a1), "r"(a2), "r"(a3), "r"(b0), "r"(b1));
}
__device__ __forceinline__ void cpa16(unsigned dst, const void* src) {
    asm volatile("cp.async.ca.shared.global [%0], [%1], 16;" :: "r"(dst), "l"(src));
}
__device__ __forceinline__ unsigned smem_u32(const void* p) {
    return (unsigned)__cvta_generic_to_shared(p);
}
__device__ __forceinline__ float ex2f(float v) {
    float r; asm("ex2.approx.f32 %0, %1;" : "=f"(r) : "f"(v)); return r;
}

// ---- packed f32x2 primitives (Blackwell dual-fp32 pipe) ----
__device__ __forceinline__ ull pk2(float a, float b) {
    ull r; asm("mov.b64 %0, {%1, %2};" : "=l"(r) : "f"(a), "f"(b)); return r;
}
__device__ __forceinline__ void upk2(ull v, float& a, float& b) {
    asm("mov.b64 {%0, %1}, %2;" : "=f"(a), "=f"(b) : "l"(v));
}
__device__ __forceinline__ ull mul2_(ull a, ull b) {
    ull r; asm("mul.rn.f32x2 %0, %1, %2;" : "=l"(r) : "l"(a), "l"(b)); return r;
}
__device__ __forceinline__ ull add2_(ull a, ull b) {
    ull r; asm("add.rn.f32x2 %0, %1, %2;" : "=l"(r) : "l"(a), "l"(b)); return r;
}
__device__ __forceinline__ ull fma2_(ull a, ull b, ull c) {
    ull r; asm("fma.rn.f32x2 %0, %1, %2, %3;" : "=l"(r) : "l"(a), "l"(b), "l"(c)); return r;
}

// ---- hybrid gate: (exp(sigmoid(z0)), exp(sigmoid(z1))).
// Both exponentials on MUFU (ex2.approx: ~1e-7 rel err; total MUFU pipe time
// ~80us chip-wide, overlappable); reciprocal stays on the fma pipe as packed
// Newton for pipe balance. gate in (0,1) -> no max-subtraction needed.
__device__ __forceinline__ ull gate_exp2(ull z) {
    const ull NL2E = pk2(-1.4426950408889634f, -1.4426950408889634f);
    const ull L2E  = pk2( 1.4426950408889634f,  1.4426950408889634f);
    const ull NONE = pk2(-1.0f, -1.0f);
    const ull ONE  = pk2(1.0f, 1.0f);
    const ull TWO  = pk2(2.0f, 2.0f);

    // u = exp(-z) = 2^(-z*log2e) via MUFU
    ull t = mul2_(z, NL2E);
    float t0, t1; upk2(t, t0, t1);
    float u0 = ex2f(t0);
    float u1 = ex2f(t1);

    // g = 1/(1+u): bit-trick seed + 2 packed Newton (~6e-6 rel err)
    ull d = add2_(ONE, pk2(u0, u1));
    float d0, d1; upk2(d, d0, d1);
    float r0 = __int_as_float(0x7EF311C3u - __float_as_int(d0));
    float r1 = __int_as_float(0x7EF311C3u - __float_as_int(d1));
    ull r  = pk2(r0, r1);
    ull nd = mul2_(d, NONE);
    r = mul2_(r, fma2_(nd, r, TWO));
    r = mul2_(r, fma2_(nd, r, TWO));

    // exp(g) = 2^(g*log2e) via MUFU
    ull v = mul2_(r, L2E);
    float v0, v1; upk2(v, v0, v1);
    return pk2(ex2f(v0), ex2f(v1));
}

// ---------------------------------------------------------------------------
// Kernel A: per-plane segment offsets via binary search on sorted idx.
// ---------------------------------------------------------------------------
__global__ void segstart_kernel(PlanePtrs p, int n)
{
    int g = blockIdx.x * blockDim.x + threadIdx.x;
    int plane = blockIdx.y;
    if (g > NG) return;

    const int* a32 = (const int*)p.idx[plane];
    bool is64 = (a32[400001] == 0);      // int64 high word 0; int32 value ~1639
    const long long* a64 = (const long long*)p.idx[plane];

    int lo = 0, hi = n;
    while (lo < hi) {
        int mid = (lo + hi) >> 1;
        long long v = is64 ? a64[mid] : (long long)a32[mid];
        if (v < (long long)g) lo = mid + 1; else hi = mid;
    }
    d_segstart[plane][g] = lo;
}

// ---------------------------------------------------------------------------
// Kernel B: fused attention pool (single launch, plane = blockIdx.y).
// One block owns SEGPB consecutive segments; cp.async pipeline runs
// continuously across segment boundaries. tf32 MMA gate GEMM + hybrid
// MUFU/packed exp(sigmoid) epilogue. W pre-arranged per block into a
// per-lane fragment table (conflict-free LDS.128).
// ---------------------------------------------------------------------------
__global__ __launch_bounds__(256, 2)
void attn_pool_kernel(PlanePtrs p)
{
    extern __shared__ char smem[];
    float*    xs[2]; xs[0] = (float*)(smem + OFF_XS0); xs[1] = (float*)(smem + OFF_XS1);
    unsigned* Wf    = (unsigned*)(smem + OFF_WF);
    float*    bs    = (float*)(smem + OFF_BS);
    float*    red_s = (float*)(smem + OFF_REDS);
    float*    red_a = (float*)(smem + OFF_REDA);
    int*      ss    = (int*)(smem + OFF_SS);

    const int plane   = blockIdx.y;
    const int segbase = blockIdx.x * SEGPB;
    const int tid  = threadIdx.x;
    const int wid  = tid >> 5;
    const int lane = tid & 31;
    const int gq   = lane >> 2;      // fragment row 0..7
    const int tig  = lane & 3;       // thread-in-group

    // Segment boundary cache for this block's range.
    if (tid <= SEGPB) ss[tid] = d_segstart[plane][segbase + tid];
    __syncthreads();

    const float* __restrict__ x = p.x[plane];

    // Lookahead tile cursor over (segment, tile) pairs; skips empty segments.
    int pseg = 0, pt = 0;
    while (pseg < SEGPB && ss[pseg] + pt * TROWS >= ss[pseg + 1]) { pseg++; pt = 0; }

    // Prefetch first tile into buf 0.
    if (pseg < SEGPB) {
        unsigned dstb = smem_u32(xs[0]);
        int nbase = ss[pseg] + pt * TROWS;
        for (int c = tid; c < TROWS * 16; c += 256) {
            int row = c >> 4, col4 = c & 15;
            int gr = min(nbase + row, NNODES - 1);
            cpa16(dstb + (unsigned)(row * XPITCH + col4 * 4) * 4u,
                  x + (size_t)gr * NF + col4 * 4);
        }
        asm volatile("cp.async.commit_group;");
        pt++;
        while (pseg < SEGPB && ss[pseg] + pt * TROWS >= ss[pseg + 1]) { pseg++; pt = 0; }
    }

    // Build per-lane W fragment table + bias while tile 0 is in flight.
    // Wf[c][w]: c = lane class (gq<<2|tig); w = nt*16 + k*2 + s;
    // value = tf32(Wg[feat=nt*8+gq][kk=k*8+tig+4s]).
    {
        const float* Wg = p.Wg[plane];
        for (int i = tid; i < 32 * 128; i += 256) {
            int c = i >> 7, w = i & 127;
            int gq_ = c >> 2, tig_ = c & 3;
            int nt = w >> 4, k = (w >> 1) & 7, s = w & 1;
            Wf[c * WFSTRIDE + w] = f2tf32(Wg[(nt * 8 + gq_) * 64 + k * 8 + tig_ + s * 4]);
        }
        if (tid < NF) bs[tid] = p.bg[plane][tid];
    }

    const int r0 = wid * 16;
    int tc = 0;                       // global tile counter -> buffer select
    const uint4* wfl = (const uint4*)(Wf + lane * WFSTRIDE);   // 16B-aligned

    ull spk[8], apk[8];
#pragma unroll
    for (int nt = 0; nt < 8; ++nt) { spk[nt] = pk2(0.f, 0.f); apk[nt] = pk2(0.f, 0.f); }

    for (int seg = 0; seg < SEGPB; ++seg) {
        const int s0 = ss[seg], s1 = ss[seg + 1];
        if (s1 <= s0) {
            if (tid < NF) d_pooled[plane][(segbase + seg) * NF + tid] = 0.f;
            continue;
        }
        const int ntiles = (s1 - s0 + TROWS - 1) / TROWS;

        for (int t = 0; t < ntiles; ++t) {
            const int buf = tc & 1;
            // Prefetch cursor tile into the other buffer (cross-segment OK).
            if (pseg < SEGPB) {
                unsigned dstb = smem_u32(xs[buf ^ 1]);
                int nbase = ss[pseg] + pt * TROWS;
                for (int c = tid; c < TROWS * 16; c += 256) {
                    int row = c >> 4, col4 = c & 15;
                    int gr = min(nbase + row, NNODES - 1);
                    cpa16(dstb + (unsigned)(row * XPITCH + col4 * 4) * 4u,
                          x + (size_t)gr * NF + col4 * 4);
                }
                asm volatile("cp.async.commit_group;");
                pt++;
                while (pseg < SEGPB && ss[pseg] + pt * TROWS >= ss[pseg + 1]) { pseg++; pt = 0; }
                asm volatile("cp.async.wait_group 1;");
            } else {
                asm volatile("cp.async.wait_group 0;");
            }
            __syncthreads();   // also publishes Wf/bs on the first iteration

            const float* xb    = xs[buf];
            const float* arow0 = xb + (r0 + gq) * XPITCH;
            const float* arow1 = xb + (r0 + gq + 8) * XPITCH;

            // A fragments: RNA tf32 conversion.
            unsigned a[8][4];
#pragma unroll
            for (int k = 0; k < 8; ++k) {
                a[k][0] = f2tf32(arow0[8 * k + tig]);
                a[k][1] = f2tf32(arow1[8 * k + tig]);
                a[k][2] = f2tf32(arow0[8 * k + tig + 4]);
                a[k][3] = f2tf32(arow1[8 * k + tig + 4]);
            }

            const int n0 = s0 + t * TROWS + r0 + gq;
            const bool v0 = (n0 < s1);
            const bool v1 = (n0 + 8 < s1);

#pragma unroll
            for (int nt = 0; nt < 8; ++nt) {
                const int f0 = nt * 8;
                // B fragments for this n-tile: 4x LDS.128, conflict-free.
                uint4 u0 = wfl[nt * 4 + 0];
                uint4 u1 = wfl[nt * 4 + 1];
                uint4 u2 = wfl[nt * 4 + 2];
                uint4 u3 = wfl[nt * 4 + 3];
                float z0 = 0.f, z1 = 0.f, z2 = 0.f, z3 = 0.f;
                mma_tf32(z0, z1, z2, z3, a[0][0], a[0][1], a[0][2], a[0][3], u0.x, u0.y);
                mma_tf32(z0, z1, z2, z3, a[1][0], a[1][1], a[1][2], a[1][3], u0.z, u0.w);
                mma_tf32(z0, z1, z2, z3, a[2][0], a[2][1], a[2][2], a[2][3], u1.x, u1.y);
                mma_tf32(z0, z1, z2, z3, a[3][0], a[3][1], a[3][2], a[3][3], u1.z, u1.w);
                mma_tf32(z0, z1, z2, z3, a[4][0], a[4][1], a[4][2], a[4][3], u2.x, u2.y);
                mma_tf32(z0, z1, z2, z3, a[5][0], a[5][1], a[5][2], a[5][3], u2.z, u2.w);
                mma_tf32(z0, z1, z2, z3, a[6][0], a[6][1], a[6][2], a[6][3], u3.x, u3.y);
                mma_tf32(z0, z1, z2, z3, a[7][0], a[7][1], a[7][2], a[7][3], u3.z, u3.w);

                ull bb  = *(const ull*)&bs[f0 + 2 * tig];
                ull e01 = gate_exp2(add2_(pk2(z0, z1), bb));   // (row n0,   feats f0+2tig,+1)
                ull e23 = gate_exp2(add2_(pk2(z2, z3), bb));   // (row n0+8)
                if (!v0) e01 = 0ull;
                if (!v1) e23 = 0ull;
                ull x01 = *(const ull*)&arow0[f0 + 2 * tig];
                ull x23 = *(const ull*)&arow1[f0 + 2 * tig];
                spk[nt] = add2_(spk[nt], add2_(e01, e23));
                apk[nt] = fma2_(e01, x01, apk[nt]);
                apk[nt] = fma2_(e23, x23, apk[nt]);
            }
            __syncthreads();   // guard xs[buf] before its next refill
            tc++;
        }

        // Per-segment reduction: shfl across the 8 quad-group rows, then
        // cross-warp via smem; reset accumulators for the next segment.
#pragma unroll
        for (int nt = 0; nt < 8; ++nt) {
            float sx, sy, ax, ay;
            upk2(spk[nt], sx, sy);
            upk2(apk[nt], ax, ay);
#pragma unroll
            for (int m = 4; m < 32; m <<= 1) {
                sx += __shfl_xor_sync(0xffffffffu, sx, m);
                sy += __shfl_xor_sync(0xffffffffu, sy, m);
                ax += __shfl_xor_sync(0xffffffffu, ax, m);
                ay += __shfl_xor_sync(0xffffffffu, ay, m);
            }
            if (gq == 0) {
                int f = nt * 8 + 2 * tig;
                red_s[wid * NF + f]     = sx;
                red_s[wid * NF + f + 1] = sy;
                red_a[wid * NF + f]     = ax;
                red_a[wid * NF + f + 1] = ay;
            }
            spk[nt] = pk2(0.f, 0.f);
            apk[nt] = pk2(0.f, 0.f);
        }
        __syncthreads();

        if (tid < NF) {
            float S = 0.f, A = 0.f;
#pragma unroll
            for (int w = 0; w < 8; ++w) {
                S += red_s[w * NF + tid];
                A += red_a[w * NF + tid];
            }
            d_pooled[plane][(segbase + seg) * NF + tid] = A / S;
        }
    }
}

// ---------------------------------------------------------------------------
// Kernel C: out[G, 256] = concat(pooled)[G, 192] @ W_out^T + b_out
// ---------------------------------------------------------------------------
__global__ __launch_bounds__(256)
void out_gemm_kernel(const float* __restrict__ W_out,
                     const float* __restrict__ b_out,
                     float* __restrict__ out)
{
    const int o  = threadIdx.x;
    const int g0 = blockIdx.x * 16;

    __shared__ float hs[16][192];
    for (int i = threadIdx.x; i < 16 * 192; i += 256) {
        int gg = i / 192, k = i % 192;
        hs[gg][k] = d_pooled[k >> 6][(g0 + gg) * NF + (k & 63)];
    }
    __syncthreads();

    float accv[16];
    const float bo = b_out[o];
#pragma unroll
    for (int gg = 0; gg < 16; ++gg) accv[gg] = bo;

    const float4* wrow = (const float4*)(W_out + o * 192);
    for (int k4 = 0; k4 < 48; ++k4) {
        float4 w = wrow[k4];
        int k = k4 * 4;
#pragma unroll
        for (int gg = 0; gg < 16; ++gg) {
            accv[gg] += w.x * hs[gg][k + 0];
            accv[gg] += w.y * hs[gg][k + 1];
            accv[gg] += w.z * hs[gg][k + 2];
            accv[gg] += w.w * hs[gg][k + 3];
        }
    }
#pragma unroll
    for (int gg = 0; gg < 16; ++gg)
        out[(g0 + gg) * NFI + o] = accv[gg];
}

// ---------------------------------------------------------------------------
// Launch: classify inputs by element count (order-robust), then 3 kernels.
// attn fused across planes in ONE launch (wave-quantization fix).
// ---------------------------------------------------------------------------
extern "C" void kernel_launch(void* const* d_in, const int* in_sizes, int n_in,
                              void* d_out, int out_size)
{
    PlanePtrs p;
    const float* W_out = nullptr;
    const float* b_out = nullptr;
    int nx = 0, nw = 0, nb = 0, ni = 0;

    for (int i = 0; i < n_in; ++i) {
        switch (in_sizes[i]) {
            case NNODES * NF:      if (nx < 3) p.x[nx++]   = (const float*)d_in[i]; break;
            case NF * NF:          if (nw < 3) p.Wg[nw++]  = (const float*)d_in[i]; break;
            case NF:               if (nb < 3) p.bg[nb++]  = (const float*)d_in[i]; break;
            case NNODES:           if (ni < 3) p.idx[ni++] = d_in[i];               break;
            case NFI * 3 * NF:     W_out = (const float*)d_in[i];                   break;
            case NFI:              b_out = (const float*)d_in[i];                   break;
            default: break;
        }
    }

    cudaFuncSetAttribute(attn_pool_kernel,
                         cudaFuncAttributeMaxDynamicSharedMemorySize, SMEM_TOTAL);

    dim3 gseg((NG + 1 + 255) / 256, 3);
    segstart_kernel<<<gseg, 256>>>(p, NNODES);

    dim3 gattn(NG / SEGPB, 3);
    attn_pool_kernel<<<gattn, 256, SMEM_TOTAL>>>(p);

    out_gemm_kernel<<<NG / 16, 256>>>(W_out, b_out, (float*)d_out);
    (void)out_size;
}

// round 15
// speedup vs baseline: 1.3394x; 1.0291x over previous
#include <cuda_runtime.h>
#include <cuda_bf16.h>

// Problem constants (fixed shapes)
#define NF       64          // planar features
#define NG       4096        // graphs / segments
#define NNODES   1000000     // nodes per plane
#define NFI      256         // interaction features

#define TROWS    128         // nodes per tile (8 warps x 16-row m16n8k8 slabs)
#define SEGPB    8           // segments per block (sorted idx -> contiguous)
#define XPITCH   68          // x smem row pitch (floats): conflict-free
#define WFSTRIDE 132         // per-lane W-fragment row stride (words): 4-bank shift

// Dynamic smem layout (bytes)
#define XS_BYTES   (TROWS * XPITCH * 4)
#define OFF_XS0    0
#define OFF_XS1    (OFF_XS0 + XS_BYTES)          // 34816
#define OFF_WF     (OFF_XS1 + XS_BYTES)          // 69632  (32*132*4 = 16896)
#define OFF_BS     (OFF_WF + 32 * WFSTRIDE * 4)  // 86528
#define OFF_REDS   (OFF_BS + 256)                // 86784
#define OFF_REDA   (OFF_REDS + 2048)             // 88832
#define OFF_SS     (OFF_REDA + 2048)             // 90880
#define SMEM_TOTAL (OFF_SS + (SEGPB + 1) * 4 + 12)   // 90928

typedef unsigned long long ull;

// -------- device scratch (no cudaMalloc allowed) --------
__device__ int   d_segstart[3][NG + 1];
__device__ float d_pooled[3][NG * NF];

struct PlanePtrs {
    const float* x[3];
    const float* Wg[3];
    const float* bg[3];
    const void*  idx[3];
};

// ---- PTX helpers ----
__device__ __forceinline__ unsigned f2tf32(float v) {
    unsigned u; asm("cvt.rna.tf32.f32 %0, %1;" : "=r"(u) : "f"(v)); return u;
}
__device__ __forceinline__ void mma_tf32(float& d0, float& d1, float& d2, float& d3,
                                         unsigned a0, unsigned a1, unsigned a2, unsigned a3,
                                         unsigned b0, unsigned b1) {
    asm volatile("mma.sync.aligned.m16n8k8.row.col.f32.tf32.tf32.f32 "
                 "{%0,%1,%2,%3}, {%4,%5,%6,%7}, {%8,%9}, {%0,%1,%2,%3};"
                 : "+f"(d0), "+f"(d1), "+f"(d2), "+f"(d3)
                 : "r"(a0), "r"(a1), "r"(a2), "r"(a3), "r"(b0), "r"(b1));
}
__device__ __forceinline__ void cpa16(unsigned dst, const void* src) {
    asm volatile("cp.async.ca.shared.global [%0], [%1], 16;" :: "r"(dst), "l"(src));
}
__device__ __forceinline__ unsigned smem_u32(const void* p) {
    return (unsigned)__cvta_generic_to_shared(p);
}
__device__ __forceinline__ float ex2f(float v) {
    float r; asm("ex2.approx.f32 %0, %1;" : "=f"(r) : "f"(v)); return r;
}

// ---- packed f32x2 primitives (Blackwell dual-fp32 pipe) ----
__device__ __forceinline__ ull pk2(float a, float b) {
    ull r; asm("mov.b64 %0, {%1, %2};" : "=l"(r) : "f"(a), "f"(b)); return r;
}
__device__ __forceinline__ void upk2(ull v, float& a, float& b) {
    asm("mov.b64 {%0, %1}, %2;" : "=f"(a), "=f"(b) : "l"(v));
}
__device__ __forceinline__ ull mul2_(ull a, ull b) {
    ull r; asm("mul.rn.f32x2 %0, %1, %2;" : "=l"(r) : "l"(a), "l"(b)); return r;
}
__device__ __forceinline__ ull add2_(ull a, ull b) {
    ull r; asm("add.rn.f32x2 %0, %1, %2;" : "=l"(r) : "l"(a), "l"(b)); return r;
}
__device__ __forceinline__ ull fma2_(ull a, ull b, ull c) {
    ull r; asm("fma.rn.f32x2 %0, %1, %2, %3;" : "=l"(r) : "l"(a), "l"(b), "l"(c)); return r;
}

// ---- hybrid gate: (exp(sigmoid(z0)), exp(sigmoid(z1))).
// Exponentials on MUFU (ex2.approx, ~1e-7 err); reciprocal stays on the fma
// pipe as packed Newton for pipe balance. gate in (0,1) -> no max needed.
__device__ __forceinline__ ull gate_exp2(ull z) {
    const ull NL2E = pk2(-1.4426950408889634f, -1.4426950408889634f);
    const ull L2E  = pk2( 1.4426950408889634f,  1.4426950408889634f);
    const ull NONE = pk2(-1.0f, -1.0f);
    const ull ONE  = pk2(1.0f, 1.0f);
    const ull TWO  = pk2(2.0f, 2.0f);

    ull t = mul2_(z, NL2E);
    float t0, t1; upk2(t, t0, t1);
    float u0 = ex2f(t0);
    float u1 = ex2f(t1);

    ull d = add2_(ONE, pk2(u0, u1));
    float d0, d1; upk2(d, d0, d1);
    float r0 = __int_as_float(0x7EF311C3u - __float_as_int(d0));
    float r1 = __int_as_float(0x7EF311C3u - __float_as_int(d1));
    ull r  = pk2(r0, r1);
    ull nd = mul2_(d, NONE);
    r = mul2_(r, fma2_(nd, r, TWO));
    r = mul2_(r, fma2_(nd, r, TWO));

    ull v = mul2_(r, L2E);
    float v0, v1; upk2(v, v0, v1);
    return pk2(ex2f(v0), ex2f(v1));
}

// ---------------------------------------------------------------------------
// Kernel A: per-plane segment offsets via binary search on sorted idx.
// ---------------------------------------------------------------------------
__global__ void segstart_kernel(PlanePtrs p, int n)
{
    int g = blockIdx.x * blockDim.x + threadIdx.x;
    int plane = blockIdx.y;
    if (g > NG) return;

    const int* a32 = (const int*)p.idx[plane];
    bool is64 = (a32[400001] == 0);      // int64 high word 0; int32 value ~1639
    const long long* a64 = (const long long*)p.idx[plane];

    int lo = 0, hi = n;
    while (lo < hi) {
        int mid = (lo + hi) >> 1;
        long long v = is64 ? a64[mid] : (long long)a32[mid];
        if (v < (long long)g) lo = mid + 1; else hi = mid;
    }
    d_segstart[plane][g] = lo;
}

// ---------------------------------------------------------------------------
// Kernel B: fused attention pool (single launch, plane = blockIdx.y).
// One block owns SEGPB consecutive segments; cp.async pipeline runs
// continuously across segment boundaries. tf32 MMA gate GEMM (raw-fp32 A
// bits — HW truncates, validated by the R7/R8 differential) + hybrid
// MUFU/packed exp(sigmoid) epilogue. Per-lane W fragment table in smem.
// Per-nt MMA accumulation split into two 4-deep chains (latency halving).
// ---------------------------------------------------------------------------
__global__ __launch_bounds__(256, 2)
void attn_pool_kernel(PlanePtrs p)
{
    extern __shared__ char smem[];
    float*    xs[2]; xs[0] = (float*)(smem + OFF_XS0); xs[1] = (float*)(smem + OFF_XS1);
    unsigned* Wf    = (unsigned*)(smem + OFF_WF);
    float*    bs    = (float*)(smem + OFF_BS);
    float*    red_s = (float*)(smem + OFF_REDS);
    float*    red_a = (float*)(smem + OFF_REDA);
    int*      ss    = (int*)(smem + OFF_SS);

    const int plane   = blockIdx.y;
    const int segbase = blockIdx.x * SEGPB;
    const int tid  = threadIdx.x;
    const int wid  = tid >> 5;
    const int lane = tid & 31;
    const int gq   = lane >> 2;      // fragment row 0..7
    const int tig  = lane & 3;       // thread-in-group

    // Segment boundary cache for this block's range.
    if (tid <= SEGPB) ss[tid] = d_segstart[plane][segbase + tid];
    __syncthreads();

    const float* __restrict__ x = p.x[plane];

    // Lookahead tile cursor over (segment, tile) pairs; skips empty segments.
    int pseg = 0, pt = 0;
    while (pseg < SEGPB && ss[pseg] + pt * TROWS >= ss[pseg + 1]) { pseg++; pt = 0; }

    // Prefetch first tile into buf 0.
    if (pseg < SEGPB) {
        unsigned dstb = smem_u32(xs[0]);
        int nbase = ss[pseg] + pt * TROWS;
        for (int c = tid; c < TROWS * 16; c += 256) {
            int row = c >> 4, col4 = c & 15;
            int gr = min(nbase + row, NNODES - 1);
            cpa16(dstb + (unsigned)(row * XPITCH + col4 * 4) * 4u,
                  x + (size_t)gr * NF + col4 * 4);
        }
        asm volatile("cp.async.commit_group;");
        pt++;
        while (pseg < SEGPB && ss[pseg] + pt * TROWS >= ss[pseg + 1]) { pseg++; pt = 0; }
    }

    // Build per-lane W fragment table + bias while tile 0 is in flight.
    // Wf[c][w]: c = lane class (gq<<2|tig); w = nt*16 + k*2 + s;
    // value = tf32(Wg[feat=nt*8+gq][kk=k*8+tig+4s]).  (B keeps RNA cvt.)
    {
        const float* Wg = p.Wg[plane];
        for (int i = tid; i < 32 * 128; i += 256) {
            int c = i >> 7, w = i & 127;
            int gq_ = c >> 2, tig_ = c & 3;
            int nt = w >> 4, k = (w >> 1) & 7, s = w & 1;
            Wf[c * WFSTRIDE + w] = f2tf32(Wg[(nt * 8 + gq_) * 64 + k * 8 + tig_ + s * 4]);
        }
        if (tid < NF) bs[tid] = p.bg[plane][tid];
    }

    const int r0 = wid * 16;
    int tc = 0;                       // global tile counter -> buffer select
    const uint4* wfl = (const uint4*)(Wf + lane * WFSTRIDE);   // 16B-aligned

    ull spk[8], apk[8];
#pragma unroll
    for (int nt = 0; nt < 8; ++nt) { spk[nt] = pk2(0.f, 0.f); apk[nt] = pk2(0.f, 0.f); }

    for (int seg = 0; seg < SEGPB; ++seg) {
        const int s0 = ss[seg], s1 = ss[seg + 1];
        if (s1 <= s0) {
            if (tid < NF) d_pooled[plane][(segbase + seg) * NF + tid] = 0.f;
            continue;
        }
        const int ntiles = (s1 - s0 + TROWS - 1) / TROWS;

        for (int t = 0; t < ntiles; ++t) {
            const int buf = tc & 1;
            // Prefetch cursor tile into the other buffer (cross-segment OK).
            if (pseg < SEGPB) {
                unsigned dstb = smem_u32(xs[buf ^ 1]);
                int nbase = ss[pseg] + pt * TROWS;
                for (int c = tid; c < TROWS * 16; c += 256) {
                    int row = c >> 4, col4 = c & 15;
                    int gr = min(nbase + row, NNODES - 1);
                    cpa16(dstb + (unsigned)(row * XPITCH + col4 * 4) * 4u,
                          x + (size_t)gr * NF + col4 * 4);
                }
                asm volatile("cp.async.commit_group;");
                pt++;
                while (pseg < SEGPB && ss[pseg] + pt * TROWS >= ss[pseg + 1]) { pseg++; pt = 0; }
                asm volatile("cp.async.wait_group 1;");
            } else {
                asm volatile("cp.async.wait_group 0;");
            }
            __syncthreads();   // also publishes Wf/bs on the first iteration

            const float* xb    = xs[buf];
            const float* arow0 = xb + (r0 + gq) * XPITCH;
            const float* arow1 = xb + (r0 + gq + 8) * XPITCH;

            // A fragments: raw fp32 bits as tf32 (HW truncation; saves the
            // cvt stage on the LDS->MMA critical path).
            unsigned a[8][4];
#pragma unroll
            for (int k = 0; k < 8; ++k) {
                a[k][0] = __float_as_uint(arow0[8 * k + tig]);
                a[k][1] = __float_as_uint(arow1[8 * k + tig]);
                a[k][2] = __float_as_uint(arow0[8 * k + tig + 4]);
                a[k][3] = __float_as_uint(arow1[8 * k + tig + 4]);
            }

            const int n0 = s0 + t * TROWS + r0 + gq;
            const bool v0 = (n0 < s1);
            const bool v1 = (n0 + 8 < s1);

#pragma unroll
            for (int nt = 0; nt < 8; ++nt) {
                const int f0 = nt * 8;
                // B fragments for this n-tile: 4x LDS.128, conflict-free.
                uint4 u0 = wfl[nt * 4 + 0];
                uint4 u1 = wfl[nt * 4 + 1];
                uint4 u2 = wfl[nt * 4 + 2];
                uint4 u3 = wfl[nt * 4 + 3];
                // Two independent 4-deep accumulation chains (even/odd k).
                float za0 = 0.f, za1 = 0.f, za2 = 0.f, za3 = 0.f;
                float zb0 = 0.f, zb1 = 0.f, zb2 = 0.f, zb3 = 0.f;
                mma_tf32(za0, za1, za2, za3, a[0][0], a[0][1], a[0][2], a[0][3], u0.x, u0.y);
                mma_tf32(zb0, zb1, zb2, zb3, a[1][0], a[1][1], a[1][2], a[1][3], u0.z, u0.w);
                mma_tf32(za0, za1, za2, za3, a[2][0], a[2][1], a[2][2], a[2][3], u1.x, u1.y);
                mma_tf32(zb0, zb1, zb2, zb3, a[3][0], a[3][1], a[3][2], a[3][3], u1.z, u1.w);
                mma_tf32(za0, za1, za2, za3, a[4][0], a[4][1], a[4][2], a[4][3], u2.x, u2.y);
                mma_tf32(zb0, zb1, zb2, zb3, a[5][0], a[5][1], a[5][2], a[5][3], u2.z, u2.w);
                mma_tf32(za0, za1, za2, za3, a[6][0], a[6][1], a[6][2], a[6][3], u3.x, u3.y);
                mma_tf32(zb0, zb1, zb2, zb3, a[7][0], a[7][1], a[7][2], a[7][3], u3.z, u3.w);

                ull bb  = *(const ull*)&bs[f0 + 2 * tig];
                ull zz01 = add2_(add2_(pk2(za0, za1), pk2(zb0, zb1)), bb);
                ull zz23 = add2_(add2_(pk2(za2, za3), pk2(zb2, zb3)), bb);
                ull e01 = gate_exp2(zz01);     // (row n0,   feats f0+2tig,+1)
                ull e23 = gate_exp2(zz23);     // (row n0+8)
                if (!v0) e01 = 0ull;
                if (!v1) e23 = 0ull;
                ull x01 = *(const ull*)&arow0[f0 + 2 * tig];
                ull x23 = *(const ull*)&arow1[f0 + 2 * tig];
                spk[nt] = add2_(spk[nt], add2_(e01, e23));
                apk[nt] = fma2_(e01, x01, apk[nt]);
                apk[nt] = fma2_(e23, x23, apk[nt]);
            }
            __syncthreads();   // guard xs[buf] before its next refill
            tc++;
        }

        // Per-segment reduction: shfl across the 8 quad-group rows, then
        // cross-warp via smem; reset accumulators for the next segment.
#pragma unroll
        for (int nt = 0; nt < 8; ++nt) {
            float sx, sy, ax, ay;
            upk2(spk[nt], sx, sy);
            upk2(apk[nt], ax, ay);
#pragma unroll
            for (int m = 4; m < 32; m <<= 1) {
                sx += __shfl_xor_sync(0xffffffffu, sx, m);
                sy += __shfl_xor_sync(0xffffffffu, sy, m);
                ax += __shfl_xor_sync(0xffffffffu, ax, m);
                ay += __shfl_xor_sync(0xffffffffu, ay, m);
            }
            if (gq == 0) {
                int f = nt * 8 + 2 * tig;
                red_s[wid * NF + f]     = sx;
                red_s[wid * NF + f + 1] = sy;
                red_a[wid * NF + f]     = ax;
                red_a[wid * NF + f + 1] = ay;
            }
            spk[nt] = pk2(0.f, 0.f);
            apk[nt] = pk2(0.f, 0.f);
        }
        __syncthreads();

        if (tid < NF) {
            float S = 0.f, A = 0.f;
#pragma unroll
            for (int w = 0; w < 8; ++w) {
                S += red_s[w * NF + tid];
                A += red_a[w * NF + tid];
            }
            d_pooled[plane][(segbase + seg) * NF + tid] = A / S;
        }
    }
}

// ---------------------------------------------------------------------------
// Kernel C: out[G, 256] = concat(pooled)[G, 192] @ W_out^T + b_out
// ---------------------------------------------------------------------------
__global__ __launch_bounds__(256)
void out_gemm_kernel(const float* __restrict__ W_out,
                     const float* __restrict__ b_out,
                     float* __restrict__ out)
{
    const int o  = threadIdx.x;
    const int g0 = blockIdx.x * 16;

    __shared__ float hs[16][192];
    for (int i = threadIdx.x; i < 16 * 192; i += 256) {
        int gg = i / 192, k = i % 192;
        hs[gg][k] = d_pooled[k >> 6][(g0 + gg) * NF + (k & 63)];
    }
    __syncthreads();

    float accv[16];
    const float bo = b_out[o];
#pragma unroll
    for (int gg = 0; gg < 16; ++gg) accv[gg] = bo;

    const float4* wrow = (const float4*)(W_out + o * 192);
    for (int k4 = 0; k4 < 48; ++k4) {
        float4 w = wrow[k4];
        int k = k4 * 4;
#pragma unroll
        for (int gg = 0; gg < 16; ++gg) {
            accv[gg] += w.x * hs[gg][k + 0];
            accv[gg] += w.y * hs[gg][k + 1];
            accv[gg] += w.z * hs[gg][k + 2];
            accv[gg] += w.w * hs[gg][k + 3];
        }
    }
#pragma unroll
    for (int gg = 0; gg < 16; ++gg)
        out[(g0 + gg) * NFI + o] = accv[gg];
}

// ---------------------------------------------------------------------------
// Launch: classify inputs by element count (order-robust), then 3 kernels.
// ---------------------------------------------------------------------------
extern "C" void kernel_launch(void* const* d_in, const int* in_sizes, int n_in,
                              void* d_out, int out_size)
{
    PlanePtrs p;
    const float* W_out = nullptr;
    const float* b_out = nullptr;
    int nx = 0, nw = 0, nb = 0, ni = 0;

    for (int i = 0; i < n_in; ++i) {
        switch (in_sizes[i]) {
            case NNODES * NF:      if (nx < 3) p.x[nx++]   = (const float*)d_in[i]; break;
            case NF * NF:          if (nw < 3) p.Wg[nw++]  = (const float*)d_in[i]; break;
            case NF:               if (nb < 3) p.bg[nb++]  = (const float*)d_in[i]; break;
            case NNODES:           if (ni < 3) p.idx[ni++] = d_in[i];               break;
            case NFI * 3 * NF:     W_out = (const float*)d_in[i];                   break;
            case NFI:              b_out = (const float*)d_in[i];                   break;
            default: break;
        }
    }

    cudaFuncSetAttribute(attn_pool_kernel,
                         cudaFuncAttributeMaxDynamicSharedMemorySize, SMEM_TOTAL);

    dim3 gseg((NG + 1 + 255) / 256, 3);
    segstart_kernel<<<gseg, 256>>>(p, NNODES);

    dim3 gattn(NG / SEGPB, 3);
    attn_pool_kernel<<<gattn, 256, SMEM_TOTAL>>>(p);

    out_gemm_kernel<<<NG / 16, 256>>>(W_out, b_out, (float*)d_out);
    (void)out_size;
}